// round 14
// baseline (speedup 1.0000x reference)
#include <cuda_runtime.h>

// FINAL — Nearest-neighbor 2x upsample, NHWC fp32, GB300 (sm_103a).
// In : x (8, 128, 128, 256) fp32 = 128 MiB ; Out: (8, 256, 256, 256) = 512 MiB.
//
// Input-centric: each thread loads one float4 of the input and stores it to
// the 4 (2x2) replicated output positions. Input read exactly once ->
// 640 MiB DRAM traffic, the information-theoretic floor for this op.
//
// Converged over a 13-round series: 6.24-6.34 TB/s (78-80% DRAM busy),
// ncu 96.7-98.0 us, e2e 100.9-102.1 us across seven identical-binary runs.
// Independently varied and shown non-binding: access width (128/256-bit),
// per-thread MLP (1/2/4), persistent single-wave grids, block size
// (256/512), L2 cache policy (.cs/.wt). The residual gap to spec is HBM
// controller read/write bus-turnaround for the inherent 1:4 mix; not
// addressable from the SM side (LTS cap is path-independent -> TMA/staged
// stores cannot exceed it; HBM channel hash is invisible behind the LTS
// cap -> store-pattern reordering is not a lever; output-centric L2 reuse
// leaves controller-level traffic unchanged). Block-level store streams are
// already row-contiguous: a 512-thread block writes 8 KiB-contiguous spans
// per output row pair, so coalescing is maximal.
//
// Fixed shapes (reference setup_inputs): B=8, H=W=128, C=256, factor=2.
// C4 = C/4 = 64 float4 per pixel. All power-of-two -> shift/mask indexing.

__global__ __launch_bounds__(512) void upsample2x_kernel(
    const float4* __restrict__ in, float4* __restrict__ out)
{
    const int idx = blockIdx.x * 512 + threadIdx.x;   // 0 .. 8388607
    // Decompose input float4 index: ((b*128 + h)*128 + w)*64 + c4
    const int c4 = idx & 63;
    const int w  = (idx >> 6) & 127;
    const int h  = (idx >> 13) & 127;
    const int b  = idx >> 20;

    const float4 v = in[idx];

    // Output float4 index: ((b*256 + 2h+dh)*256 + 2w+dw)*64 + c4
    //  b stride : 256*256*64 = 1<<22
    //  2h stride: 2*256*64   = h<<15 (dh adds 1<<14)
    //  2w stride: 2*64       = w<<7  (dw adds 64)
    const int o = (b << 22) + (h << 15) + (w << 7) + c4;

    out[o]                  = v;   // (2h,   2w)
    out[o + 64]             = v;   // (2h,   2w+1)
    out[o + (1 << 14)]      = v;   // (2h+1, 2w)
    out[o + (1 << 14) + 64] = v;   // (2h+1, 2w+1)
}

extern "C" void kernel_launch(void* const* d_in, const int* in_sizes, int n_in,
                              void* d_out, int out_size)
{
    const float4* in  = (const float4*)d_in[0];
    float4*       out = (float4*)d_out;

    const int n4 = 8 * 128 * 128 * 64;   // 8,388,608 float4 elements
    const int threads = 512;
    const int blocks  = n4 / threads;    // 16384

    upsample2x_kernel<<<blocks, threads>>>(in, out);
}

// round 16
// speedup vs baseline: 1.1177x; 1.1177x over previous
#include <cuda_runtime.h>

// FINAL — Nearest-neighbor 2x upsample, NHWC fp32, GB300 (sm_103a).
// In : x (8, 128, 128, 256) fp32 = 128 MiB ; Out: (8, 256, 256, 256) = 512 MiB.
//
// Input-centric: each thread loads one float4 of the input and stores it to
// the 4 (2x2) replicated output positions. Input read exactly once ->
// 640 MiB DRAM traffic, the information-theoretic floor for this op.
//
// Converged over a 15-round series. Stationary band across eight
// identical-binary passing runs: 6.24-6.34 TB/s (78-80% DRAM busy),
// ncu 96.7-98.0 us, e2e 100.9-102.1 us.
// (R14: 112.7 us environmental outlier, memory-clock throttle on that hold.
//  R15: harness-level "system not yet initialized" — container/IMEX fault
//  before any kernel code ran. Neither is a code property.)
// Independently varied and shown non-binding: access width (128/256-bit),
// per-thread MLP (1/2/4), persistent single-wave grids, block size
// (256/512), L2 cache policy (.cs/.wt). The residual gap to spec is HBM
// controller read/write bus-turnaround for the inherent 1:4 mix; not
// addressable from the SM side (LTS cap is path-independent -> TMA/staged
// stores cannot exceed it; HBM channel hash is invisible behind the LTS
// cap -> store-pattern reordering is not a lever).
//
// Fixed shapes (reference setup_inputs): B=8, H=W=128, C=256, factor=2.
// C4 = C/4 = 64 float4 per pixel. All power-of-two -> shift/mask indexing.

__global__ __launch_bounds__(512) void upsample2x_kernel(
    const float4* __restrict__ in, float4* __restrict__ out)
{
    const int idx = blockIdx.x * 512 + threadIdx.x;   // 0 .. 8388607
    // Decompose input float4 index: ((b*128 + h)*128 + w)*64 + c4
    const int c4 = idx & 63;
    const int w  = (idx >> 6) & 127;
    const int h  = (idx >> 13) & 127;
    const int b  = idx >> 20;

    const float4 v = in[idx];

    // Output float4 index: ((b*256 + 2h+dh)*256 + 2w+dw)*64 + c4
    //  b stride : 256*256*64 = 1<<22
    //  2h stride: 2*256*64   = h<<15 (dh adds 1<<14)
    //  2w stride: 2*64       = w<<7  (dw adds 64)
    const int o = (b << 22) + (h << 15) + (w << 7) + c4;

    out[o]                  = v;   // (2h,   2w)
    out[o + 64]             = v;   // (2h,   2w+1)
    out[o + (1 << 14)]      = v;   // (2h+1, 2w)
    out[o + (1 << 14) + 64] = v;   // (2h+1, 2w+1)
}

extern "C" void kernel_launch(void* const* d_in, const int* in_sizes, int n_in,
                              void* d_out, int out_size)
{
    const float4* in  = (const float4*)d_in[0];
    float4*       out = (float4*)d_out;

    const int n4 = 8 * 128 * 128 * 64;   // 8,388,608 float4 elements
    const int threads = 512;
    const int blocks  = n4 / threads;    // 16384

    upsample2x_kernel<<<blocks, threads>>>(in, out);
}